// round 6
// baseline (speedup 1.0000x reference)
#include <cuda_runtime.h>
#include <cuda_fp16.h>
#include <cstdint>

// ---------------- device scratch (no allocation allowed) ----------------------
__device__ unsigned g_h1[65536 * 8];      // packed layer-1 sign bits [row][8]
__device__ __half   g_w1h[256 * 784];     // sign(w1) as fp16 +-1, [n][k]
__device__ unsigned g_w2t[8 * 128];       // packed sign(w2), transposed [word][j]
__device__ unsigned g_w3t[4 * 32];        // packed sign(w3), transposed [word][n]
__device__ unsigned g_w4p[16];            // packed sign(w4) rows

// ---------------- PTX helpers (base sm_103-legal only) -------------------------
__device__ __forceinline__ uint32_t smem_u32(const void* p) {
    uint32_t a;
    asm("{ .reg .u64 t; cvta.to.shared.u64 t, %1; cvt.u32.u64 %0, t; }" : "=r"(a) : "l"(p));
    return a;
}
#define LDSM4(r, addr)                                                          \
    asm volatile("ldmatrix.sync.aligned.m8n8.x4.shared.b16 {%0,%1,%2,%3}, [%4];"\
        : "=r"((r)[0]), "=r"((r)[1]), "=r"((r)[2]), "=r"((r)[3]) : "r"(addr))
#define MMA16816(d, a, b0, b1)                                                  \
    asm volatile("mma.sync.aligned.m16n8k16.row.col.f32.f16.f16.f32 "           \
        "{%0,%1,%2,%3}, {%4,%5,%6,%7}, {%8,%9}, {%0,%1,%2,%3};"                 \
        : "+f"((d)[0]), "+f"((d)[1]), "+f"((d)[2]), "+f"((d)[3])                \
        : "r"((a)[0]), "r"((a)[1]), "r"((a)[2]), "r"((a)[3]), "r"(b0), "r"(b1))
#define CP16(dst, src)                                                          \
    asm volatile("cp.async.cg.shared.global [%0], [%1], 16;" :: "r"(dst), "l"(src))
#define CP_COMMIT() asm volatile("cp.async.commit_group;" ::: "memory")
#define CP_WAIT0()  asm volatile("cp.async.wait_group 0;" ::: "memory")

// ---------------- borderline oracle: EXACT round-1/4 arithmetic ----------------
// Sequential fp32 FFMA chain over k ascending; validated against the reference
// in rounds 1 and 4 (rel_err == 0.0 both times).
__device__ __noinline__ float seqdot(const float* __restrict__ x,
                                     const float* __restrict__ w1,
                                     int r, int n) {
    const float* xr = x  + (size_t)r * 784;
    const float* wr = w1 + (size_t)n * 784;
    float s = 0.0f;
    #pragma unroll 4
    for (int k = 0; k < 784; k++) {
        float w = (__ldg(wr + k) >= 0.0f) ? 1.0f : -1.0f;
        s = fmaf(__ldg(xr + k), w, s);
    }
    return s;
}

// ---------------- prep: sign(w1) -> fp16 +-1 -----------------------------------
__global__ void prep_w1h(const float* __restrict__ w1) {
    int i = blockIdx.x * blockDim.x + threadIdx.x;
    if (i < 256 * 784)
        g_w1h[i] = __float2half_rn((w1[i] >= 0.0f) ? 1.0f : -1.0f);
}

// ---------------- prep: bit-pack w2/w3/w4 (transposed layouts) -----------------
__global__ void pack_w(const float* __restrict__ w2,
                       const float* __restrict__ w3,
                       const float* __restrict__ w4) {
    int t = blockIdx.x * blockDim.x + threadIdx.x;
    if (t < 1024) {                          // w2t[w][j]
        int w = t / 128, j = t % 128;
        unsigned v = 0;
        #pragma unroll
        for (int b = 0; b < 32; b++)
            v |= (w2[j * 256 + w * 32 + b] >= 0.0f) ? (1u << b) : 0u;
        g_w2t[t] = v;
    } else if (t < 1024 + 128) {             // w3t[w][n]
        int u = t - 1024;
        int w = u / 32, n = u % 32;
        unsigned v = 0;
        #pragma unroll
        for (int b = 0; b < 32; b++)
            v |= (w3[n * 128 + w * 32 + b] >= 0.0f) ? (1u << b) : 0u;
        g_w3t[u] = v;
    } else if (t < 1024 + 128 + 10) {        // w4
        int r = t - 1152;
        unsigned v = 0;
        #pragma unroll
        for (int b = 0; b < 32; b++)
            v |= (w4[r * 32 + b] >= 0.0f) ? (1u << b) : 0u;
        g_w4p[r] = v;
    }
}

// ---------------- layer 1: hi-only HMMA GEMM + bound + worklist fixup ----------
// CTA tile 64(M) x 256(N); K = 7 chunks of 112. Warp tile 32x64 (2x4 warps).
// smem per stage: Ahi[64][120]h (15360) | B[256][120]h (61440) => 76800
static constexpr int STAGE = 76800;
static constexpr int SMEM_TOTAL = 2 * STAGE;   // 153600

__global__ __launch_bounds__(256, 1) void l1_gemm(const float* __restrict__ x,
                                                  const float* __restrict__ w1) {
    extern __shared__ char smem[];
    __shared__ float    rbnd[64];          // per-row sum of |lo|
    __shared__ unsigned wcnt;
    __shared__ unsigned wl[2048];          // borderline worklist (row<<16 | col)

    const uint32_t sbase = smem_u32(smem);
    const int tid  = threadIdx.x;
    const int lane = tid & 31;
    const int wid  = tid >> 5;
    const int wm   = wid & 1;          // M half (rows 32*wm..)
    const int wn   = wid >> 1;         // N block of 64
    const int rowBase = blockIdx.x * 64;

    if (tid < 64) rbnd[tid] = 0.0f;
    if (tid == 0) wcnt = 0;

    float acc[2][8][4];
    #pragma unroll
    for (int mi = 0; mi < 2; mi++)
        #pragma unroll
        for (int nf = 0; nf < 8; nf++)
            #pragma unroll
            for (int q = 0; q < 4; q++) acc[mi][nf][q] = 0.0f;

    float bnd[7];                      // |lo| partials; entry i -> row (tid+256i)/28
    #pragma unroll
    for (int i = 0; i < 7; i++) bnd[i] = 0.0f;

    // ldmatrix per-thread offsets (R4-proven)
    const uint32_t aoff = (uint32_t)((lane & 15) * 240 + (lane >> 4) * 16 + wm * 7680);
    const uint32_t boff = (uint32_t)(((lane & 7) + ((lane >> 4) & 1) * 8) * 240
                                     + ((lane >> 3) & 1) * 16 + wn * 15360);

    float4 fr[7];

    auto ldgA = [&](int c) {
        #pragma unroll
        for (int i = 0; i < 7; i++) {
            int g = tid + 256 * i;
            int row = g / 28, c4 = g % 28;
            fr[i] = *reinterpret_cast<const float4*>(
                &x[(size_t)(rowBase + row) * 784 + c * 112 + c4 * 4]);
        }
    };
    auto stsA = [&](int buf) {
        const uint32_t sAhi = sbase + buf * STAGE;
        #pragma unroll
        for (int i = 0; i < 7; i++) {
            int g = tid + 256 * i;
            int row = g / 28, c4 = g % 28;
            float4 f = fr[i];
            __half2 h01 = __floats2half2_rn(f.x, f.y);
            __half2 h23 = __floats2half2_rn(f.z, f.w);
            float2 b01 = __half22float2(h01);
            float2 b23 = __half22float2(h23);
            bnd[i] += fabsf(f.x - b01.x) + fabsf(f.y - b01.y)
                    + fabsf(f.z - b23.x) + fabsf(f.w - b23.y);
            uint32_t uh0 = *reinterpret_cast<uint32_t*>(&h01);
            uint32_t uh1 = *reinterpret_cast<uint32_t*>(&h23);
            asm volatile("st.shared.v2.b32 [%0], {%1,%2};"
                         :: "r"(sAhi + (uint32_t)(row * 240 + c4 * 8)), "r"(uh0), "r"(uh1)
                         : "memory");
        }
    };
    auto cpB = [&](int c, int buf) {
        const uint32_t sB = sbase + buf * STAGE + 15360;
        #pragma unroll
        for (int i = 0; i < 14; i++) {
            int g = tid + 256 * i;
            int row = g / 14, c16 = g % 14;
            CP16(sB + (uint32_t)(row * 240 + c16 * 16),
                 (const void*)(&g_w1h[(size_t)row * 784 + c * 112 + c16 * 8]));
        }
    };
    auto compute = [&](int buf) {
        const uint32_t sAhi = sbase + buf * STAGE;
        const uint32_t sB   = sAhi + 15360;
        #pragma unroll
        for (int ks = 0; ks < 7; ks++) {
            uint32_t ah0[4], ah1[4], bf[4][4];
            LDSM4(ah0, sAhi + aoff + ks * 32);
            LDSM4(ah1, sAhi + aoff + 3840 + ks * 32);
            #pragma unroll
            for (int nbp = 0; nbp < 4; nbp++)
                LDSM4(bf[nbp], sB + boff + nbp * 3840 + ks * 32);
            #pragma unroll
            for (int nf = 0; nf < 8; nf++) {
                uint32_t b0 = bf[nf >> 1][(nf & 1) * 2];
                uint32_t b1 = bf[nf >> 1][(nf & 1) * 2 + 1];
                MMA16816(acc[0][nf], ah0, b0, b1);
                MMA16816(acc[1][nf], ah1, b0, b1);
            }
        }
    };

    // ---- prologue: chunk 0 ----
    ldgA(0);
    cpB(0, 0);
    CP_COMMIT();
    stsA(0);
    CP_WAIT0();
    __syncthreads();

    // ---- main loop (R4-proven schedule) ----
    for (int c = 0; c < 7; c++) {
        int cur = c & 1;
        if (c < 6) { ldgA(c + 1); cpB(c + 1, cur ^ 1); CP_COMMIT(); }
        compute(cur);
        if (c < 6) { stsA(cur ^ 1); CP_WAIT0(); __syncthreads(); }
    }

    // ---- epilogue ----
    __syncthreads();                        // all compute done; reuse smem
    {
        #pragma unroll
        for (int i = 0; i < 7; i++) {
            int row = (tid + 256 * i) / 28;
            atomicAdd(&rbnd[row], bnd[i]);
        }
    }
    __syncthreads();

    // pass 1: provisional signs + flag borderline into worklist
    char* sb = smem;                        // 64 x 256 bytes
    #pragma unroll
    for (int mi = 0; mi < 2; mi++) {
        #pragma unroll
        for (int nf = 0; nf < 8; nf++) {
            #pragma unroll
            for (int q = 0; q < 4; q++) {
                float v = acc[mi][nf][q];
                int rl = wm * 32 + mi * 16 + (lane >> 2) + ((q >> 1) << 3);
                int cc = wn * 64 + nf * 8 + (lane & 3) * 2 + (q & 1);
                if (fabsf(v) < rbnd[rl] + 2e-3f) {
                    unsigned idx = atomicAdd(&wcnt, 1u);
                    if (idx < 2048)
                        wl[idx] = ((unsigned)rl << 16) | (unsigned)cc;
                    else                    // overflow fallback: resolve inline
                        v = seqdot(x, w1, rowBase + rl, cc);
                }
                sb[rl * 256 + cc] = (v >= 0.0f) ? 1 : 0;
            }
        }
    }
    __syncthreads();

    // pass 2: resolve flagged dots with the reference-order oracle (parallel)
    {
        unsigned cnt = wcnt;
        if (cnt > 2048) cnt = 2048;
        for (unsigned e = tid; e < cnt; e += 256) {
            unsigned ent = wl[e];
            int rl = (int)(ent >> 16), cc = (int)(ent & 0xFFFF);
            float v = seqdot(x, w1, rowBase + rl, cc);
            sb[rl * 256 + cc] = (v >= 0.0f) ? 1 : 0;
        }
    }
    __syncthreads();

    // pack 512 words (64 rows x 8 words), 2 per thread
    const unsigned* sbu = reinterpret_cast<const unsigned*>(sb);
    #pragma unroll
    for (int s = 0; s < 2; s++) {
        int q = tid + s * 256;
        int r = q >> 3, w = q & 7;
        unsigned v = 0;
        #pragma unroll
        for (int j = 0; j < 8; j++) {
            unsigned u = sbu[r * 64 + w * 8 + j];
            v |= (((u & 0x01010101u) * 0x01020408u) >> 24) << (j * 4);
        }
        g_h1[(size_t)(rowBase + r) * 8 + w] = v;
    }
}

// ---------------- layers 2-4: XNOR-popcount, conflict-free smem ----------------
__global__ __launch_bounds__(256) void l234(float* __restrict__ out, int M) {
    __shared__ unsigned sw2[1024];   // [w][j]
    __shared__ unsigned sw3[128];    // [w][n]
    __shared__ unsigned sw4[10];
    int tid = threadIdx.x;
    for (int i = tid; i < 1024; i += 256) sw2[i] = g_w2t[i];
    if (tid < 128) sw3[tid] = g_w3t[tid];
    if (tid < 10)  sw4[tid] = g_w4p[tid];
    __syncthreads();

    int warp = (blockIdx.x * 256 + tid) >> 5;
    int lane = tid & 31;
    if (warp >= M) return;

    unsigned a[8];
    uint4 a0 = *reinterpret_cast<const uint4*>(&g_h1[(size_t)warp * 8]);
    uint4 a1 = *reinterpret_cast<const uint4*>(&g_h1[(size_t)warp * 8 + 4]);
    a[0]=a0.x; a[1]=a0.y; a[2]=a0.z; a[3]=a0.w;
    a[4]=a1.x; a[5]=a1.y; a[6]=a1.z; a[7]=a1.w;

    unsigned h2w[4];
    #pragma unroll
    for (int q = 0; q < 4; q++) {
        int j = q * 32 + lane;
        int p = 0;
        #pragma unroll
        for (int w = 0; w < 8; w++) p += __popc(a[w] ^ sw2[w * 128 + j]);
        h2w[q] = __ballot_sync(0xffffffffu, (256 - 2 * p) >= 0);
    }

    int p3 = 0;
    #pragma unroll
    for (int w = 0; w < 4; w++) p3 += __popc(h2w[w] ^ sw3[w * 32 + lane]);
    unsigned h3 = __ballot_sync(0xffffffffu, (128 - 2 * p3) >= 0);

    if (lane < 10)
        out[(size_t)warp * 10 + lane] = (float)(32 - 2 * __popc(h3 ^ sw4[lane]));
}

// ---------------- launch ------------------------------------------------------
extern "C" void kernel_launch(void* const* d_in, const int* in_sizes, int n_in,
                              void* d_out, int out_size) {
    const float* x  = (const float*)d_in[0];
    const float* w1 = (const float*)d_in[1];
    const float* w2 = (const float*)d_in[2];
    const float* w3 = (const float*)d_in[3];
    const float* w4 = (const float*)d_in[4];
    int M = in_sizes[0] / 784;             // 65536

    cudaFuncSetAttribute(l1_gemm, cudaFuncAttributeMaxDynamicSharedMemorySize, SMEM_TOTAL);

    prep_w1h<<<(256 * 784 + 255) / 256, 256>>>(w1);
    pack_w<<<5, 256>>>(w2, w3, w4);
    l1_gemm<<<M / 64, 256, SMEM_TOTAL>>>(x, w1);
    l234<<<(M + 7) / 8, 256>>>((float*)d_out, M);
}

// round 7
// speedup vs baseline: 1.8311x; 1.8311x over previous
#include <cuda_runtime.h>
#include <cuda_fp16.h>
#include <cstdint>

// ---------------- device scratch (no allocation allowed) ----------------------
__device__ unsigned g_h1[65536 * 8];      // packed layer-1 sign bits [row][8]
__device__ __half   g_w1h[256 * 784];     // sign(w1) as fp16 +-1, [n][k]
__device__ __half   g_xlo[65536ULL * 784];// lo residual of x (fp16), [row][k]
__device__ unsigned g_w1p[256 * 25];      // packed sign(w1) bits, [n][25 words]
__device__ unsigned g_w2t[8 * 128];       // packed sign(w2), transposed [word][j]
__device__ unsigned g_w3t[4 * 32];        // packed sign(w3), transposed [word][n]
__device__ unsigned g_w4p[16];            // packed sign(w4) rows

// ---------------- PTX helpers (base sm_103-legal only) -------------------------
__device__ __forceinline__ uint32_t smem_u32(const void* p) {
    uint32_t a;
    asm("{ .reg .u64 t; cvta.to.shared.u64 t, %1; cvt.u32.u64 %0, t; }" : "=r"(a) : "l"(p));
    return a;
}
#define LDSM4(r, addr)                                                          \
    asm volatile("ldmatrix.sync.aligned.m8n8.x4.shared.b16 {%0,%1,%2,%3}, [%4];"\
        : "=r"((r)[0]), "=r"((r)[1]), "=r"((r)[2]), "=r"((r)[3]) : "r"(addr))
#define MMA16816(d, a, b0, b1)                                                  \
    asm volatile("mma.sync.aligned.m16n8k16.row.col.f32.f16.f16.f32 "           \
        "{%0,%1,%2,%3}, {%4,%5,%6,%7}, {%8,%9}, {%0,%1,%2,%3};"                 \
        : "+f"((d)[0]), "+f"((d)[1]), "+f"((d)[2]), "+f"((d)[3])                \
        : "r"((a)[0]), "r"((a)[1]), "r"((a)[2]), "r"((a)[3]), "r"(b0), "r"(b1))
#define CP16(dst, src)                                                          \
    asm volatile("cp.async.cg.shared.global [%0], [%1], 16;" :: "r"(dst), "l"(src))
#define CP_COMMIT() asm volatile("cp.async.commit_group;" ::: "memory")
#define CP_WAIT0()  asm volatile("cp.async.wait_group 0;" ::: "memory")

// ---------------- slow global oracle (overflow fallback only) ------------------
__device__ __noinline__ float seqdot(const float* __restrict__ x,
                                     const float* __restrict__ w1,
                                     int r, int n) {
    const float* xr = x  + (size_t)r * 784;
    const float* wr = w1 + (size_t)n * 784;
    float s = 0.0f;
    #pragma unroll 4
    for (int k = 0; k < 784; k++) {
        float w = (__ldg(wr + k) >= 0.0f) ? 1.0f : -1.0f;
        s = fmaf(__ldg(xr + k), w, s);
    }
    return s;
}

// ---------------- prep: sign(w1) -> fp16 +-1 and packed bits -------------------
__global__ void prep_w1h(const float* __restrict__ w1) {
    int i = blockIdx.x * blockDim.x + threadIdx.x;
    if (i < 256 * 784)
        g_w1h[i] = __float2half_rn((w1[i] >= 0.0f) ? 1.0f : -1.0f);
    if (i < 256 * 25) {                      // packed: bit b of word j = sign(w1[n][32j+b])
        int n = i / 25, j = i % 25;
        unsigned v = 0;
        #pragma unroll
        for (int b = 0; b < 32; b++) {
            int k = j * 32 + b;
            if (k < 784 && w1[n * 784 + k] >= 0.0f) v |= (1u << b);
        }
        g_w1p[i] = v;
    }
}

// ---------------- prep: bit-pack w2/w3/w4 (transposed layouts) -----------------
__global__ void pack_w(const float* __restrict__ w2,
                       const float* __restrict__ w3,
                       const float* __restrict__ w4) {
    int t = blockIdx.x * blockDim.x + threadIdx.x;
    if (t < 1024) {                          // w2t[w][j]
        int w = t / 128, j = t % 128;
        unsigned v = 0;
        #pragma unroll
        for (int b = 0; b < 32; b++)
            v |= (w2[j * 256 + w * 32 + b] >= 0.0f) ? (1u << b) : 0u;
        g_w2t[t] = v;
    } else if (t < 1024 + 128) {             // w3t[w][n]
        int u = t - 1024;
        int w = u / 32, n = u % 32;
        unsigned v = 0;
        #pragma unroll
        for (int b = 0; b < 32; b++)
            v |= (w3[n * 128 + w * 32 + b] >= 0.0f) ? (1u << b) : 0u;
        g_w3t[u] = v;
    } else if (t < 1024 + 128 + 10) {        // w4
        int r = t - 1152;
        unsigned v = 0;
        #pragma unroll
        for (int b = 0; b < 32; b++)
            v |= (w4[r * 32 + b] >= 0.0f) ? (1u << b) : 0u;
        g_w4p[r] = v;
    }
}

// ---------------- layer 1: hi-only HMMA GEMM + two-tier fixup ------------------
// CTA tile 64(M) x 256(N); K = 7 chunks of 112. Warp tile 32x64 (2x4 warps).
// smem per stage: Ahi[64][120]h (15360) | B[256][120]h (61440) => 76800
static constexpr int STAGE = 76800;
static constexpr int SMEM_TOTAL = 2 * STAGE;   // 153600

__global__ __launch_bounds__(256, 1) void l1_gemm(const float* __restrict__ x,
                                                  const float* __restrict__ w1) {
    extern __shared__ char smem[];
    __shared__ float    rbnd[64];          // per-row sum of |lo|
    __shared__ unsigned wcnt;
    __shared__ unsigned wl[2048];          // borderline worklist (row<<16 | col)
    __shared__ float    wlv[2048];         // hi-MMA acc value of flagged entry

    const uint32_t sbase = smem_u32(smem);
    const int tid  = threadIdx.x;
    const int lane = tid & 31;
    const int wid  = tid >> 5;
    const int wm   = wid & 1;
    const int wn   = wid >> 1;
    const int rowBase = blockIdx.x * 64;

    if (tid < 64) rbnd[tid] = 0.0f;
    if (tid == 0) wcnt = 0;

    float acc[2][8][4];
    #pragma unroll
    for (int mi = 0; mi < 2; mi++)
        #pragma unroll
        for (int nf = 0; nf < 8; nf++)
            #pragma unroll
            for (int q = 0; q < 4; q++) acc[mi][nf][q] = 0.0f;

    float bnd[7];
    #pragma unroll
    for (int i = 0; i < 7; i++) bnd[i] = 0.0f;

    const uint32_t aoff = (uint32_t)((lane & 15) * 240 + (lane >> 4) * 16 + wm * 7680);
    const uint32_t boff = (uint32_t)(((lane & 7) + ((lane >> 4) & 1) * 8) * 240
                                     + ((lane >> 3) & 1) * 16 + wn * 15360);

    float4 fr[7];

    auto ldgA = [&](int c) {
        #pragma unroll
        for (int i = 0; i < 7; i++) {
            int g = tid + 256 * i;
            int row = g / 28, c4 = g % 28;
            fr[i] = *reinterpret_cast<const float4*>(
                &x[(size_t)(rowBase + row) * 784 + c * 112 + c4 * 4]);
        }
    };
    auto stsA = [&](int c, int buf) {
        const uint32_t sAhi = sbase + buf * STAGE;
        #pragma unroll
        for (int i = 0; i < 7; i++) {
            int g = tid + 256 * i;
            int row = g / 28, c4 = g % 28;
            float4 f = fr[i];
            __half2 h01 = __floats2half2_rn(f.x, f.y);
            __half2 h23 = __floats2half2_rn(f.z, f.w);
            float2 b01 = __half22float2(h01);
            float2 b23 = __half22float2(h23);
            float d0 = f.x - b01.x, d1 = f.y - b01.y;
            float d2 = f.z - b23.x, d3 = f.w - b23.y;
            bnd[i] += fabsf(d0) + fabsf(d1) + fabsf(d2) + fabsf(d3);
            // store lo residual to global scratch (exact fp16 of fp32 diff)
            __half2 l01 = __floats2half2_rn(d0, d1);
            __half2 l23 = __floats2half2_rn(d2, d3);
            *reinterpret_cast<__half2*>(
                &g_xlo[(size_t)(rowBase + row) * 784 + c * 112 + c4 * 4]) = l01;
            *reinterpret_cast<__half2*>(
                &g_xlo[(size_t)(rowBase + row) * 784 + c * 112 + c4 * 4 + 2]) = l23;
            uint32_t uh0 = *reinterpret_cast<uint32_t*>(&h01);
            uint32_t uh1 = *reinterpret_cast<uint32_t*>(&h23);
            asm volatile("st.shared.v2.b32 [%0], {%1,%2};"
                         :: "r"(sAhi + (uint32_t)(row * 240 + c4 * 8)), "r"(uh0), "r"(uh1)
                         : "memory");
        }
    };
    auto cpB = [&](int c, int buf) {
        const uint32_t sB = sbase + buf * STAGE + 15360;
        #pragma unroll
        for (int i = 0; i < 14; i++) {
            int g = tid + 256 * i;
            int row = g / 14, c16 = g % 14;
            CP16(sB + (uint32_t)(row * 240 + c16 * 16),
                 (const void*)(&g_w1h[(size_t)row * 784 + c * 112 + c16 * 8]));
        }
    };
    auto compute = [&](int buf) {
        const uint32_t sAhi = sbase + buf * STAGE;
        const uint32_t sB   = sAhi + 15360;
        #pragma unroll
        for (int ks = 0; ks < 7; ks++) {
            uint32_t ah0[4], ah1[4], bf[4][4];
            LDSM4(ah0, sAhi + aoff + ks * 32);
            LDSM4(ah1, sAhi + aoff + 3840 + ks * 32);
            #pragma unroll
            for (int nbp = 0; nbp < 4; nbp++)
                LDSM4(bf[nbp], sB + boff + nbp * 3840 + ks * 32);
            #pragma unroll
            for (int nf = 0; nf < 8; nf++) {
                uint32_t b0 = bf[nf >> 1][(nf & 1) * 2];
                uint32_t b1 = bf[nf >> 1][(nf & 1) * 2 + 1];
                MMA16816(acc[0][nf], ah0, b0, b1);
                MMA16816(acc[1][nf], ah1, b0, b1);
            }
        }
    };

    // ---- prologue: chunk 0 ----
    ldgA(0);
    cpB(0, 0);
    CP_COMMIT();
    stsA(0, 0);
    CP_WAIT0();
    __syncthreads();

    // ---- main loop (proven schedule) ----
    for (int c = 0; c < 7; c++) {
        int cur = c & 1;
        if (c < 6) { ldgA(c + 1); cpB(c + 1, cur ^ 1); CP_COMMIT(); }
        compute(cur);
        if (c < 6) { stsA(c + 1, cur ^ 1); CP_WAIT0(); __syncthreads(); }
    }

    // ---- epilogue ----
    __syncthreads();
    {
        #pragma unroll
        for (int i = 0; i < 7; i++) {
            int row = (tid + 256 * i) / 28;
            atomicAdd(&rbnd[row], bnd[i]);
        }
    }
    __syncthreads();

    // pass 1: provisional signs + flag borderline into worklist
    char* sb = smem;                        // 64 x 256 bytes
    #pragma unroll
    for (int mi = 0; mi < 2; mi++) {
        #pragma unroll
        for (int nf = 0; nf < 8; nf++) {
            #pragma unroll
            for (int q = 0; q < 4; q++) {
                float v = acc[mi][nf][q];
                int rl = wm * 32 + mi * 16 + (lane >> 2) + ((q >> 1) << 3);
                int cc = wn * 64 + nf * 8 + (lane & 3) * 2 + (q & 1);
                if (fabsf(v) < rbnd[rl] + 1e-3f) {
                    unsigned idx = atomicAdd(&wcnt, 1u);
                    if (idx < 2048) {
                        wl[idx]  = ((unsigned)rl << 16) | (unsigned)cc;
                        wlv[idx] = v;
                    } else {                // overflow: resolve inline (rare)
                        v = seqdot(x, w1, rowBase + rl, cc);
                    }
                }
                sb[rl * 256 + cc] = (v >= 0.0f) ? 1 : 0;
            }
        }
    }
    __syncthreads();

    // pass 2: warp-cooperative fixup
    {
        unsigned cnt = wcnt;
        if (cnt > 2048) cnt = 2048;
        for (unsigned e = wid; e < cnt; e += 8) {
            unsigned ent = wl[e];
            int rl = (int)(ent >> 16), cc = (int)(ent & 0xFFFF);
            // 2a: exact lo correction (order-insensitive small term)
            const __half* lorow = &g_xlo[(size_t)(rowBase + rl) * 784];
            float part = 0.0f;
            #pragma unroll
            for (int j = 0; j < 25; j++) {
                int k = lane + 32 * j;
                if (k < 784) {
                    float lo = __half2float(__ldg(lorow + k));
                    unsigned wb = __ldg(&g_w1p[cc * 25 + j]);
                    part += ((wb >> lane) & 1u) ? lo : -lo;
                }
            }
            #pragma unroll
            for (int o = 16; o; o >>= 1)
                part += __shfl_xor_sync(0xffffffffu, part, o);
            float v = wlv[e] + part;        // == hi+lo full value (R4-class)
            if (fabsf(v) >= 1e-3f) {
                if (lane == 0) sb[rl * 256 + cc] = (v >= 0.0f) ? 1 : 0;
            } else {
                // 2b: staged sequential-order oracle (reference-validated order)
                float* xbuf = reinterpret_cast<float*>(smem + 16384 + wid * 8192);
                float* gbuf = xbuf + 784;
                const float* xr = x + (size_t)(rowBase + rl) * 784;
                for (int k = lane; k < 784; k += 32) {
                    xbuf[k] = __ldg(xr + k);
                    unsigned wb = __ldg(&g_w1p[cc * 25 + (k >> 5)]);
                    gbuf[k] = ((wb >> (k & 31)) & 1u) ? 1.0f : -1.0f;
                }
                __syncwarp();
                if (lane == 0) {
                    float s = 0.0f;
                    #pragma unroll 8
                    for (int k = 0; k < 784; k++)
                        s = fmaf(xbuf[k], gbuf[k], s);
                    sb[rl * 256 + cc] = (s >= 0.0f) ? 1 : 0;
                }
                __syncwarp();
            }
        }
    }
    __syncthreads();

    // pack 512 words (64 rows x 8 words), 2 per thread
    const unsigned* sbu = reinterpret_cast<const unsigned*>(sb);
    #pragma unroll
    for (int s = 0; s < 2; s++) {
        int q = tid + s * 256;
        int r = q >> 3, w = q & 7;
        unsigned v = 0;
        #pragma unroll
        for (int j = 0; j < 8; j++) {
            unsigned u = sbu[r * 64 + w * 8 + j];
            v |= (((u & 0x01010101u) * 0x01020408u) >> 24) << (j * 4);
        }
        g_h1[(size_t)(rowBase + r) * 8 + w] = v;
    }
}

// ---------------- layers 2-4: XNOR-popcount, conflict-free smem ----------------
__global__ __launch_bounds__(256) void l234(float* __restrict__ out, int M) {
    __shared__ unsigned sw2[1024];   // [w][j]
    __shared__ unsigned sw3[128];    // [w][n]
    __shared__ unsigned sw4[10];
    int tid = threadIdx.x;
    for (int i = tid; i < 1024; i += 256) sw2[i] = g_w2t[i];
    if (tid < 128) sw3[tid] = g_w3t[tid];
    if (tid < 10)  sw4[tid] = g_w4p[tid];
    __syncthreads();

    int warp = (blockIdx.x * 256 + tid) >> 5;
    int lane = tid & 31;
    if (warp >= M) return;

    unsigned a[8];
    uint4 a0 = *reinterpret_cast<const uint4*>(&g_h1[(size_t)warp * 8]);
    uint4 a1 = *reinterpret_cast<const uint4*>(&g_h1[(size_t)warp * 8 + 4]);
    a[0]=a0.x; a[1]=a0.y; a[2]=a0.z; a[3]=a0.w;
    a[4]=a1.x; a[5]=a1.y; a[6]=a1.z; a[7]=a1.w;

    unsigned h2w[4];
    #pragma unroll
    for (int q = 0; q < 4; q++) {
        int j = q * 32 + lane;
        int p = 0;
        #pragma unroll
        for (int w = 0; w < 8; w++) p += __popc(a[w] ^ sw2[w * 128 + j]);
        h2w[q] = __ballot_sync(0xffffffffu, (256 - 2 * p) >= 0);
    }

    int p3 = 0;
    #pragma unroll
    for (int w = 0; w < 4; w++) p3 += __popc(h2w[w] ^ sw3[w * 32 + lane]);
    unsigned h3 = __ballot_sync(0xffffffffu, (128 - 2 * p3) >= 0);

    if (lane < 10)
        out[(size_t)warp * 10 + lane] = (float)(32 - 2 * __popc(h3 ^ sw4[lane]));
}

// ---------------- launch ------------------------------------------------------
extern "C" void kernel_launch(void* const* d_in, const int* in_sizes, int n_in,
                              void* d_out, int out_size) {
    const float* x  = (const float*)d_in[0];
    const float* w1 = (const float*)d_in[1];
    const float* w2 = (const float*)d_in[2];
    const float* w3 = (const float*)d_in[3];
    const float* w4 = (const float*)d_in[4];
    int M = in_sizes[0] / 784;             // 65536

    cudaFuncSetAttribute(l1_gemm, cudaFuncAttributeMaxDynamicSharedMemorySize, SMEM_TOTAL);

    prep_w1h<<<(256 * 784 + 255) / 256, 256>>>(w1);
    pack_w<<<5, 256>>>(w2, w3, w4);
    l1_gemm<<<M / 64, 256, SMEM_TOTAL>>>(x, w1);
    l234<<<(M + 7) / 8, 256>>>((float*)d_out, M);
}

// round 8
// speedup vs baseline: 2.3344x; 1.2749x over previous
#include <cuda_runtime.h>
#include <cuda_fp16.h>
#include <cstdint>

// ---------------- device scratch (no allocation allowed) ----------------------
__device__ __half   g_w1h[256 * 832];     // sign(w1) as fp16 +-1, [n][k], K padded
__device__ __half   g_xlo[65536ULL * 784];// lo residual of x (fp16), [row][k]
__device__ unsigned g_w1p[256 * 25];      // packed sign(w1) bits, [n][25 words]
__device__ unsigned g_w2t[8 * 128];       // packed sign(w2), transposed [word][j]
__device__ unsigned g_w3t[4 * 32];        // packed sign(w3), transposed [word][n]
__device__ unsigned g_w4p[16];            // packed sign(w4) rows

// ---------------- PTX helpers (base sm_103-legal only) -------------------------
__device__ __forceinline__ uint32_t smem_u32(const void* p) {
    uint32_t a;
    asm("{ .reg .u64 t; cvta.to.shared.u64 t, %1; cvt.u32.u64 %0, t; }" : "=r"(a) : "l"(p));
    return a;
}
#define LDSM4(r, addr)                                                          \
    asm volatile("ldmatrix.sync.aligned.m8n8.x4.shared.b16 {%0,%1,%2,%3}, [%4];"\
        : "=r"((r)[0]), "=r"((r)[1]), "=r"((r)[2]), "=r"((r)[3]) : "r"(addr))
#define MMA16816(d, a, b0, b1)                                                  \
    asm volatile("mma.sync.aligned.m16n8k16.row.col.f32.f16.f16.f32 "           \
        "{%0,%1,%2,%3}, {%4,%5,%6,%7}, {%8,%9}, {%0,%1,%2,%3};"                 \
        : "+f"((d)[0]), "+f"((d)[1]), "+f"((d)[2]), "+f"((d)[3])                \
        : "r"((a)[0]), "r"((a)[1]), "r"((a)[2]), "r"((a)[3]), "r"(b0), "r"(b1))
#define CP16(dst, src)                                                          \
    asm volatile("cp.async.cg.shared.global [%0], [%1], 16;" :: "r"(dst), "l"(src))
#define CP_COMMIT() asm volatile("cp.async.commit_group;" ::: "memory")
#define CP_WAIT0()  asm volatile("cp.async.wait_group 0;" ::: "memory")

// ---------------- slow global oracle (worklist-overflow fallback only) ---------
__device__ __noinline__ float seqdot(const float* __restrict__ x,
                                     const float* __restrict__ w1,
                                     int r, int n) {
    const float* xr = x  + (size_t)r * 784;
    const float* wr = w1 + (size_t)n * 784;
    float s = 0.0f;
    #pragma unroll 4
    for (int k = 0; k < 784; k++) {
        float w = (__ldg(wr + k) >= 0.0f) ? 1.0f : -1.0f;
        s = fmaf(__ldg(xr + k), w, s);
    }
    return s;
}

// ---------------- prep: sign(w1) -> fp16 +-1 (padded) and packed bits ----------
__global__ void prep_w1h(const float* __restrict__ w1) {
    int i = blockIdx.x * blockDim.x + threadIdx.x;
    if (i < 256 * 832) {
        int n = i / 832, k = i % 832;
        float v = (k < 784) ? ((w1[n * 784 + k] >= 0.0f) ? 1.0f : -1.0f) : 0.0f;
        g_w1h[i] = __float2half_rn(v);
    }
    if (i < 256 * 25) {
        int n = i / 25, j = i % 25;
        unsigned v = 0;
        #pragma unroll
        for (int b = 0; b < 32; b++) {
            int k = j * 32 + b;
            if (k < 784 && w1[n * 784 + k] >= 0.0f) v |= (1u << b);
        }
        g_w1p[i] = v;
    }
}

// ---------------- prep: bit-pack w2/w3/w4 (transposed layouts) -----------------
__global__ void pack_w(const float* __restrict__ w2,
                       const float* __restrict__ w3,
                       const float* __restrict__ w4) {
    int t = blockIdx.x * blockDim.x + threadIdx.x;
    if (t < 1024) {                          // w2t[w][j]
        int w = t / 128, j = t % 128;
        unsigned v = 0;
        #pragma unroll
        for (int b = 0; b < 32; b++)
            v |= (w2[j * 256 + w * 32 + b] >= 0.0f) ? (1u << b) : 0u;
        g_w2t[t] = v;
    } else if (t < 1024 + 128) {             // w3t[w][n]
        int u = t - 1024;
        int w = u / 32, n = u % 32;
        unsigned v = 0;
        #pragma unroll
        for (int b = 0; b < 32; b++)
            v |= (w3[n * 128 + w * 32 + b] >= 0.0f) ? (1u << b) : 0u;
        g_w3t[u] = v;
    } else if (t < 1024 + 128 + 10) {        // w4
        int r = t - 1152;
        unsigned v = 0;
        #pragma unroll
        for (int b = 0; b < 32; b++)
            v |= (w4[r * 32 + b] >= 0.0f) ? (1u << b) : 0u;
        g_w4p[r] = v;
    }
}

// ---------------- fused: hi-only HMMA GEMM + fixup + layers 2-4 ----------------
// CTA tile 64(M) x 256(N); K = 13 chunks of 64 (padded to 832). 2 CTAs/SM.
// stage: A[64][72h=144B] (9216) | B[256][144B] (36864) => 46080
static constexpr int PITCH   = 144;
static constexpr int A_BYTES = 64 * PITCH;            // 9216
static constexpr int STAGE   = A_BYTES + 256 * PITCH; // 46080
static constexpr int SMEM_TOTAL = 2 * STAGE;          // 92160
static constexpr int WLCAP = 1536;

__global__ __launch_bounds__(256, 2) void l1_fused(const float* __restrict__ x,
                                                   const float* __restrict__ w1,
                                                   float* __restrict__ out) {
    extern __shared__ char smem[];
    __shared__ float    rbnd[64];
    __shared__ unsigned wcnt;
    __shared__ unsigned wl[WLCAP];
    __shared__ float    wlv[WLCAP];

    const uint32_t sbase = smem_u32(smem);
    const int tid  = threadIdx.x;
    const int lane = tid & 31;
    const int wid  = tid >> 5;
    const int wm   = wid & 1;          // M half (rows 32*wm..)
    const int wn   = wid >> 1;         // N block of 64
    const int rowBase = blockIdx.x * 64;

    if (tid < 64) rbnd[tid] = 0.0f;
    if (tid == 0) wcnt = 0;

    float acc[2][8][4];
    #pragma unroll
    for (int mi = 0; mi < 2; mi++)
        #pragma unroll
        for (int nf = 0; nf < 8; nf++)
            #pragma unroll
            for (int q = 0; q < 4; q++) acc[mi][nf][q] = 0.0f;

    float bnd[4];
    #pragma unroll
    for (int i = 0; i < 4; i++) bnd[i] = 0.0f;

    const uint32_t aoff = (uint32_t)((lane & 15) * PITCH + (lane >> 4) * 16 + wm * 32 * PITCH);
    const uint32_t boff = (uint32_t)(((lane & 7) + ((lane >> 4) & 1) * 8) * PITCH
                                     + ((lane >> 3) & 1) * 16 + wn * 64 * PITCH);

    float4 fr[4];

    auto ldgA = [&](int c) {
        #pragma unroll
        for (int i = 0; i < 4; i++) {
            int g = tid + 256 * i;                  // 1024 float4
            int row = g >> 4, c4 = g & 15;
            int kf = c * 64 + c4 * 4;
            if (kf < 784)
                fr[i] = *reinterpret_cast<const float4*>(
                    &x[(size_t)(rowBase + row) * 784 + kf]);
            else
                fr[i] = make_float4(0.f, 0.f, 0.f, 0.f);
        }
    };
    auto stsA = [&](int c, int buf) {
        const uint32_t sA = sbase + buf * STAGE;
        #pragma unroll
        for (int i = 0; i < 4; i++) {
            int g = tid + 256 * i;
            int row = g >> 4, c4 = g & 15;
            int kf = c * 64 + c4 * 4;
            float4 f = fr[i];
            __half2 h01 = __floats2half2_rn(f.x, f.y);
            __half2 h23 = __floats2half2_rn(f.z, f.w);
            float2 b01 = __half22float2(h01);
            float2 b23 = __half22float2(h23);
            float d0 = f.x - b01.x, d1 = f.y - b01.y;
            float d2 = f.z - b23.x, d3 = f.w - b23.y;
            bnd[i] += fabsf(d0) + fabsf(d1) + fabsf(d2) + fabsf(d3);
            if (kf < 784) {
                __half2 l01 = __floats2half2_rn(d0, d1);
                __half2 l23 = __floats2half2_rn(d2, d3);
                *reinterpret_cast<__half2*>(
                    &g_xlo[(size_t)(rowBase + row) * 784 + kf]) = l01;
                *reinterpret_cast<__half2*>(
                    &g_xlo[(size_t)(rowBase + row) * 784 + kf + 2]) = l23;
            }
            uint32_t uh0 = *reinterpret_cast<uint32_t*>(&h01);
            uint32_t uh1 = *reinterpret_cast<uint32_t*>(&h23);
            asm volatile("st.shared.v2.b32 [%0], {%1,%2};"
                         :: "r"(sA + (uint32_t)(row * PITCH + c4 * 8)), "r"(uh0), "r"(uh1)
                         : "memory");
        }
    };
    auto cpB = [&](int c, int buf) {
        const uint32_t sB = sbase + buf * STAGE + A_BYTES;
        #pragma unroll
        for (int i = 0; i < 8; i++) {
            int g = tid + 256 * i;                  // 2048 x 16B
            int row = g >> 3, c16 = g & 7;
            CP16(sB + (uint32_t)(row * PITCH + c16 * 16),
                 (const void*)(&g_w1h[(size_t)row * 832 + c * 64 + c16 * 8]));
        }
    };
    auto compute = [&](int buf) {
        const uint32_t sA = sbase + buf * STAGE;
        const uint32_t sB = sA + A_BYTES;
        #pragma unroll
        for (int ks = 0; ks < 4; ks++) {
            uint32_t ah0[4], ah1[4], bf[4][4];
            LDSM4(ah0, sA + aoff + ks * 32);
            LDSM4(ah1, sA + aoff + 16 * PITCH + ks * 32);
            #pragma unroll
            for (int nbp = 0; nbp < 4; nbp++)
                LDSM4(bf[nbp], sB + boff + nbp * 16 * PITCH + ks * 32);
            #pragma unroll
            for (int nf = 0; nf < 8; nf++) {
                uint32_t b0 = bf[nf >> 1][(nf & 1) * 2];
                uint32_t b1 = bf[nf >> 1][(nf & 1) * 2 + 1];
                MMA16816(acc[0][nf], ah0, b0, b1);
                MMA16816(acc[1][nf], ah1, b0, b1);
            }
        }
    };

    // ---- prologue: chunk 0 ----
    ldgA(0);
    cpB(0, 0);
    CP_COMMIT();
    stsA(0, 0);
    CP_WAIT0();
    __syncthreads();

    // ---- main loop (proven 2-stage schedule) ----
    for (int c = 0; c < 13; c++) {
        int cur = c & 1;
        if (c < 12) { ldgA(c + 1); cpB(c + 1, cur ^ 1); CP_COMMIT(); }
        compute(cur);
        if (c < 12) { stsA(c + 1, cur ^ 1); CP_WAIT0(); __syncthreads(); }
    }

    // ---- epilogue layout in dynamic smem ----
    // sb [0,16384) | pk [16384,18432) | sw2 [18432,22528) | sw3 [22528,23040)
    // sw4 [23040,23080) | per-warp oracle buffers at [24576 + wid*8192)
    char*     sb  = smem;
    unsigned* pk  = reinterpret_cast<unsigned*>(smem + 16384);
    unsigned* sw2 = reinterpret_cast<unsigned*>(smem + 18432);
    unsigned* sw3 = reinterpret_cast<unsigned*>(smem + 22528);
    unsigned* sw4 = reinterpret_cast<unsigned*>(smem + 23040);

    __syncthreads();
    {
        #pragma unroll
        for (int i = 0; i < 4; i++) {
            int row = (tid + 256 * i) >> 4;
            atomicAdd(&rbnd[row], bnd[i]);
        }
    }
    __syncthreads();

    // pass 1: provisional signs + flag borderline
    #pragma unroll
    for (int mi = 0; mi < 2; mi++) {
        #pragma unroll
        for (int nf = 0; nf < 8; nf++) {
            #pragma unroll
            for (int q = 0; q < 4; q++) {
                float v = acc[mi][nf][q];
                int rl = wm * 32 + mi * 16 + (lane >> 2) + ((q >> 1) << 3);
                int cc = wn * 64 + nf * 8 + (lane & 3) * 2 + (q & 1);
                if (fabsf(v) < rbnd[rl] + 1e-3f) {
                    unsigned idx = atomicAdd(&wcnt, 1u);
                    if (idx < WLCAP) {
                        wl[idx]  = ((unsigned)rl << 16) | (unsigned)cc;
                        wlv[idx] = v;
                    } else {
                        v = seqdot(x, w1, rowBase + rl, cc);
                    }
                }
                sb[rl * 256 + cc] = (v >= 0.0f) ? 1 : 0;
            }
        }
    }
    __syncthreads();

    // pass 2: warp-cooperative fixup (2a exact lo-correction, 2b seq oracle)
    {
        unsigned cnt = wcnt;
        if (cnt > WLCAP) cnt = WLCAP;
        for (unsigned e = wid; e < cnt; e += 8) {
            unsigned ent = wl[e];
            int rl = (int)(ent >> 16), cc = (int)(ent & 0xFFFF);
            const __half* lorow = &g_xlo[(size_t)(rowBase + rl) * 784];
            float part = 0.0f;
            #pragma unroll
            for (int j = 0; j < 25; j++) {
                int k = lane + 32 * j;
                if (k < 784) {
                    float lo = __half2float(__ldg(lorow + k));
                    unsigned wb = __ldg(&g_w1p[cc * 25 + j]);
                    part += ((wb >> lane) & 1u) ? lo : -lo;
                }
            }
            #pragma unroll
            for (int o = 16; o; o >>= 1)
                part += __shfl_xor_sync(0xffffffffu, part, o);
            float v = wlv[e] + part;
            if (fabsf(v) >= 1e-3f) {
                if (lane == 0) sb[rl * 256 + cc] = (v >= 0.0f) ? 1 : 0;
            } else {
                float* xbuf = reinterpret_cast<float*>(smem + 24576 + wid * 8192);
                float* gbuf = xbuf + 784;
                const float* xr = x + (size_t)(rowBase + rl) * 784;
                for (int k = lane; k < 784; k += 32) {
                    xbuf[k] = __ldg(xr + k);
                    unsigned wb = __ldg(&g_w1p[cc * 25 + (k >> 5)]);
                    gbuf[k] = ((wb >> (k & 31)) & 1u) ? 1.0f : -1.0f;
                }
                __syncwarp();
                if (lane == 0) {
                    float s = 0.0f;
                    #pragma unroll 8
                    for (int k = 0; k < 784; k++)
                        s = fmaf(xbuf[k], gbuf[k], s);
                    sb[rl * 256 + cc] = (s >= 0.0f) ? 1 : 0;
                }
                __syncwarp();
            }
        }
    }
    // load packed w2/w3/w4 while fixup settles
    for (int i = tid; i < 1024; i += 256) sw2[i] = g_w2t[i];
    if (tid < 128) sw3[tid] = g_w3t[tid];
    if (tid < 10)  sw4[tid] = g_w4p[tid];
    __syncthreads();

    // pack 512 words (64 rows x 8 words), 2 per thread -> smem pk
    const unsigned* sbu = reinterpret_cast<const unsigned*>(sb);
    #pragma unroll
    for (int s = 0; s < 2; s++) {
        int q = tid + s * 256;
        int r = q >> 3, w = q & 7;
        unsigned v = 0;
        #pragma unroll
        for (int j = 0; j < 8; j++) {
            unsigned u = sbu[r * 64 + w * 8 + j];
            v |= (((u & 0x01010101u) * 0x01020408u) >> 24) << (j * 4);
        }
        pk[r * 8 + w] = v;
    }
    __syncthreads();

    // ---- fused layers 2-4: warp per row, 8 rows per warp ----
    for (int r = wid; r < 64; r += 8) {
        unsigned a0 = pk[r * 8 + 0], a1 = pk[r * 8 + 1], a2 = pk[r * 8 + 2], a3 = pk[r * 8 + 3];
        unsigned a4 = pk[r * 8 + 4], a5 = pk[r * 8 + 5], a6 = pk[r * 8 + 6], a7 = pk[r * 8 + 7];

        unsigned h2w[4];
        #pragma unroll
        for (int q = 0; q < 4; q++) {
            int j = q * 32 + lane;
            int p = __popc(a0 ^ sw2[0 * 128 + j]) + __popc(a1 ^ sw2[1 * 128 + j])
                  + __popc(a2 ^ sw2[2 * 128 + j]) + __popc(a3 ^ sw2[3 * 128 + j])
                  + __popc(a4 ^ sw2[4 * 128 + j]) + __popc(a5 ^ sw2[5 * 128 + j])
                  + __popc(a6 ^ sw2[6 * 128 + j]) + __popc(a7 ^ sw2[7 * 128 + j]);
            h2w[q] = __ballot_sync(0xffffffffu, (256 - 2 * p) >= 0);
        }

        int p3 = 0;
        #pragma unroll
        for (int w = 0; w < 4; w++) p3 += __popc(h2w[w] ^ sw3[w * 32 + lane]);
        unsigned h3 = __ballot_sync(0xffffffffu, (128 - 2 * p3) >= 0);

        if (lane < 10)
            out[(size_t)(rowBase + r) * 10 + lane] =
                (float)(32 - 2 * __popc(h3 ^ sw4[lane]));
    }
}

// ---------------- launch ------------------------------------------------------
extern "C" void kernel_launch(void* const* d_in, const int* in_sizes, int n_in,
                              void* d_out, int out_size) {
    const float* x  = (const float*)d_in[0];
    const float* w1 = (const float*)d_in[1];
    const float* w2 = (const float*)d_in[2];
    const float* w3 = (const float*)d_in[3];
    const float* w4 = (const float*)d_in[4];
    int M = in_sizes[0] / 784;             // 65536

    cudaFuncSetAttribute(l1_fused, cudaFuncAttributeMaxDynamicSharedMemorySize, SMEM_TOTAL);

    prep_w1h<<<(256 * 832 + 255) / 256, 256>>>(w1);
    pack_w<<<5, 256>>>(w2, w3, w4);
    l1_fused<<<M / 64, 256, SMEM_TOTAL>>>(x, w1, (float*)d_out);
}

// round 9
// speedup vs baseline: 2.7275x; 1.1684x over previous
#include <cuda_runtime.h>
#include <cuda_fp16.h>
#include <cstdint>

// ---------------- device scratch (no allocation allowed) ----------------------
__device__ __half   g_w1h[256 * 832];     // sign(w1) as fp16 +-1, [n][k], K padded
__device__ unsigned g_w1p[256 * 25];      // packed sign(w1) bits, [n][25 words]
__device__ unsigned g_w2t[8 * 128];       // packed sign(w2), transposed [word][j]
__device__ unsigned g_w3t[4 * 32];        // packed sign(w3), transposed [word][n]
__device__ unsigned g_w4p[16];            // packed sign(w4) rows

// ---------------- PTX helpers (base sm_103-legal only) -------------------------
__device__ __forceinline__ uint32_t smem_u32(const void* p) {
    uint32_t a;
    asm("{ .reg .u64 t; cvta.to.shared.u64 t, %1; cvt.u32.u64 %0, t; }" : "=r"(a) : "l"(p));
    return a;
}
#define LDSM4(r, addr)                                                          \
    asm volatile("ldmatrix.sync.aligned.m8n8.x4.shared.b16 {%0,%1,%2,%3}, [%4];"\
        : "=r"((r)[0]), "=r"((r)[1]), "=r"((r)[2]), "=r"((r)[3]) : "r"(addr))
#define MMA16816(d, a, b0, b1)                                                  \
    asm volatile("mma.sync.aligned.m16n8k16.row.col.f32.f16.f16.f32 "           \
        "{%0,%1,%2,%3}, {%4,%5,%6,%7}, {%8,%9}, {%0,%1,%2,%3};"                 \
        : "+f"((d)[0]), "+f"((d)[1]), "+f"((d)[2]), "+f"((d)[3])                \
        : "r"((a)[0]), "r"((a)[1]), "r"((a)[2]), "r"((a)[3]), "r"(b0), "r"(b1))
#define CP16(dst, src)                                                          \
    asm volatile("cp.async.cg.shared.global [%0], [%1], 16;" :: "r"(dst), "l"(src))
#define CP_COMMIT() asm volatile("cp.async.commit_group;" ::: "memory")
#define CP_WAIT0()  asm volatile("cp.async.wait_group 0;" ::: "memory")

// ---------------- slow global oracle (worklist-overflow fallback only) ---------
__device__ __noinline__ float seqdot(const float* __restrict__ x,
                                     const float* __restrict__ w1,
                                     int r, int n) {
    const float* xr = x  + (size_t)r * 784;
    const float* wr = w1 + (size_t)n * 784;
    float s = 0.0f;
    #pragma unroll 4
    for (int k = 0; k < 784; k++) {
        float w = (__ldg(wr + k) >= 0.0f) ? 1.0f : -1.0f;
        s = fmaf(__ldg(xr + k), w, s);
    }
    return s;
}

// ---------------- prep (merged): w1 -> fp16 +-1 (padded), all packed bits ------
__global__ void prep_all(const float* __restrict__ w1,
                         const float* __restrict__ w2,
                         const float* __restrict__ w3,
                         const float* __restrict__ w4) {
    int i = blockIdx.x * blockDim.x + threadIdx.x;
    // g_w1h: 4 halves per thread; 256*832/4 = 53248 threads
    if (i < 53248) {
        int n = i / 208, q = i % 208;
        int k = q * 4;
        __half2 h01, h23;
        if (k + 3 < 784) {
            float4 f = *reinterpret_cast<const float4*>(&w1[n * 784 + k]);
            h01 = __floats2half2_rn((f.x >= 0.0f) ? 1.0f : -1.0f,
                                    (f.y >= 0.0f) ? 1.0f : -1.0f);
            h23 = __floats2half2_rn((f.z >= 0.0f) ? 1.0f : -1.0f,
                                    (f.w >= 0.0f) ? 1.0f : -1.0f);
        } else {
            h01 = __floats2half2_rn(0.f, 0.f);
            h23 = h01;
        }
        uint2 v;
        v.x = *reinterpret_cast<uint32_t*>(&h01);
        v.y = *reinterpret_cast<uint32_t*>(&h23);
        *reinterpret_cast<uint2*>(&g_w1h[n * 832 + k]) = v;
    }
    // g_w1p
    if (i < 256 * 25) {
        int n = i / 25, j = i % 25;
        unsigned v = 0;
        #pragma unroll
        for (int b = 0; b < 32; b++) {
            int k = j * 32 + b;
            if (k < 784 && w1[n * 784 + k] >= 0.0f) v |= (1u << b);
        }
        g_w1p[i] = v;
    }
    // g_w2t / g_w3t / g_w4p
    if (i < 1024) {
        int w = i / 128, j = i % 128;
        unsigned v = 0;
        #pragma unroll
        for (int b = 0; b < 32; b++)
            v |= (w2[j * 256 + w * 32 + b] >= 0.0f) ? (1u << b) : 0u;
        g_w2t[i] = v;
    }
    if (i >= 1024 && i < 1024 + 128) {
        int u = i - 1024;
        int w = u / 32, n = u % 32;
        unsigned v = 0;
        #pragma unroll
        for (int b = 0; b < 32; b++)
            v |= (w3[n * 128 + w * 32 + b] >= 0.0f) ? (1u << b) : 0u;
        g_w3t[u] = v;
    }
    if (i >= 1024 + 128 && i < 1024 + 128 + 10) {
        int r = i - 1152;
        unsigned v = 0;
        #pragma unroll
        for (int b = 0; b < 32; b++)
            v |= (w4[r * 32 + b] >= 0.0f) ? (1u << b) : 0u;
        g_w4p[r] = v;
    }
}

// ---------------- fused: hi-only HMMA GEMM + fixup + layers 2-4 ----------------
// CTA tile 64(M) x 256(N); K = 13 chunks of 64 (padded to 832). 2 CTAs/SM.
// stage: A[64][72h=144B] (9216) | B[256][144B] (36864) => 46080
static constexpr int PITCH   = 144;
static constexpr int A_BYTES = 64 * PITCH;            // 9216
static constexpr int STAGE   = A_BYTES + 256 * PITCH; // 46080
static constexpr int SMEM_TOTAL = 2 * STAGE;          // 92160
static constexpr int WLCAP = 1536;

__global__ __launch_bounds__(256, 2) void l1_fused(const float* __restrict__ x,
                                                   const float* __restrict__ w1,
                                                   float* __restrict__ out) {
    extern __shared__ char smem[];
    __shared__ float    rbnd[64];
    __shared__ unsigned wcnt;
    __shared__ unsigned wl[WLCAP];
    __shared__ float    wlv[WLCAP];

    const uint32_t sbase = smem_u32(smem);
    const int tid  = threadIdx.x;
    const int lane = tid & 31;
    const int wid  = tid >> 5;
    const int wm   = wid & 1;          // M half (rows 32*wm..)
    const int wn   = wid >> 1;         // N block of 64
    const int rowBase = blockIdx.x * 64;

    if (tid < 64) rbnd[tid] = 0.0f;
    if (tid == 0) wcnt = 0;

    float acc[2][8][4];
    #pragma unroll
    for (int mi = 0; mi < 2; mi++)
        #pragma unroll
        for (int nf = 0; nf < 8; nf++)
            #pragma unroll
            for (int q = 0; q < 4; q++) acc[mi][nf][q] = 0.0f;

    float bnd[4];
    #pragma unroll
    for (int i = 0; i < 4; i++) bnd[i] = 0.0f;

    const uint32_t aoff = (uint32_t)((lane & 15) * PITCH + (lane >> 4) * 16 + wm * 32 * PITCH);
    const uint32_t boff = (uint32_t)(((lane & 7) + ((lane >> 4) & 1) * 8) * PITCH
                                     + ((lane >> 3) & 1) * 16 + wn * 64 * PITCH);

    float4 fr[4];

    auto ldgA = [&](int c) {
        #pragma unroll
        for (int i = 0; i < 4; i++) {
            int g = tid + 256 * i;                  // 1024 float4
            int row = g >> 4, c4 = g & 15;
            int kf = c * 64 + c4 * 4;
            if (kf < 784)
                fr[i] = *reinterpret_cast<const float4*>(
                    &x[(size_t)(rowBase + row) * 784 + kf]);
            else
                fr[i] = make_float4(0.f, 0.f, 0.f, 0.f);
        }
    };
    auto stsA = [&](int buf) {
        const uint32_t sA = sbase + buf * STAGE;
        #pragma unroll
        for (int i = 0; i < 4; i++) {
            int g = tid + 256 * i;
            int row = g >> 4, c4 = g & 15;
            float4 f = fr[i];
            __half2 h01 = __floats2half2_rn(f.x, f.y);
            __half2 h23 = __floats2half2_rn(f.z, f.w);
            float2 b01 = __half22float2(h01);
            float2 b23 = __half22float2(h23);
            bnd[i] += fabsf(f.x - b01.x) + fabsf(f.y - b01.y)
                    + fabsf(f.z - b23.x) + fabsf(f.w - b23.y);
            uint32_t uh0 = *reinterpret_cast<uint32_t*>(&h01);
            uint32_t uh1 = *reinterpret_cast<uint32_t*>(&h23);
            asm volatile("st.shared.v2.b32 [%0], {%1,%2};"
                         :: "r"(sA + (uint32_t)(row * PITCH + c4 * 8)), "r"(uh0), "r"(uh1)
                         : "memory");
        }
    };
    auto cpB = [&](int c, int buf) {
        const uint32_t sB = sbase + buf * STAGE + A_BYTES;
        #pragma unroll
        for (int i = 0; i < 8; i++) {
            int g = tid + 256 * i;                  // 2048 x 16B
            int row = g >> 3, c16 = g & 7;
            CP16(sB + (uint32_t)(row * PITCH + c16 * 16),
                 (const void*)(&g_w1h[(size_t)row * 832 + c * 64 + c16 * 8]));
        }
    };
    auto compute = [&](int buf) {
        const uint32_t sA = sbase + buf * STAGE;
        const uint32_t sB = sA + A_BYTES;
        #pragma unroll
        for (int ks = 0; ks < 4; ks++) {
            uint32_t ah0[4], ah1[4], bf[4][4];
            LDSM4(ah0, sA + aoff + ks * 32);
            LDSM4(ah1, sA + aoff + 16 * PITCH + ks * 32);
            #pragma unroll
            for (int nbp = 0; nbp < 4; nbp++)
                LDSM4(bf[nbp], sB + boff + nbp * 16 * PITCH + ks * 32);
            #pragma unroll
            for (int nf = 0; nf < 8; nf++) {
                uint32_t b0 = bf[nf >> 1][(nf & 1) * 2];
                uint32_t b1 = bf[nf >> 1][(nf & 1) * 2 + 1];
                MMA16816(acc[0][nf], ah0, b0, b1);
                MMA16816(acc[1][nf], ah1, b0, b1);
            }
        }
    };

    // ---- prologue: chunk 0 ----
    ldgA(0);
    cpB(0, 0);
    CP_COMMIT();
    stsA(0);
    CP_WAIT0();
    __syncthreads();

    // ---- main loop (proven 2-stage schedule) ----
    for (int c = 0; c < 13; c++) {
        int cur = c & 1;
        if (c < 12) { ldgA(c + 1); cpB(c + 1, cur ^ 1); CP_COMMIT(); }
        compute(cur);
        if (c < 12) { stsA(cur ^ 1); CP_WAIT0(); __syncthreads(); }
    }

    // ---- epilogue layout in dynamic smem ----
    // sb [0,16384) | pk [16384,18432) | sw2 [18432,22528) | sw3 [22528,23040)
    // sw4 [23040,23080) | per-warp oracle buffers at [24576 + wid*8192)
    char*     sb  = smem;
    unsigned* pk  = reinterpret_cast<unsigned*>(smem + 16384);
    unsigned* sw2 = reinterpret_cast<unsigned*>(smem + 18432);
    unsigned* sw3 = reinterpret_cast<unsigned*>(smem + 22528);
    unsigned* sw4 = reinterpret_cast<unsigned*>(smem + 23040);

    __syncthreads();
    {
        #pragma unroll
        for (int i = 0; i < 4; i++) {
            int row = (tid + 256 * i) >> 4;
            atomicAdd(&rbnd[row], bnd[i]);
        }
    }
    __syncthreads();

    // pass 1: provisional signs + flag borderline
    #pragma unroll
    for (int mi = 0; mi < 2; mi++) {
        #pragma unroll
        for (int nf = 0; nf < 8; nf++) {
            #pragma unroll
            for (int q = 0; q < 4; q++) {
                float v = acc[mi][nf][q];
                int rl = wm * 32 + mi * 16 + (lane >> 2) + ((q >> 1) << 3);
                int cc = wn * 64 + nf * 8 + (lane & 3) * 2 + (q & 1);
                if (fabsf(v) < rbnd[rl] + 1e-3f) {
                    unsigned idx = atomicAdd(&wcnt, 1u);
                    if (idx < WLCAP) {
                        wl[idx]  = ((unsigned)rl << 16) | (unsigned)cc;
                        wlv[idx] = v;
                    } else {
                        v = seqdot(x, w1, rowBase + rl, cc);
                    }
                }
                sb[rl * 256 + cc] = (v >= 0.0f) ? 1 : 0;
            }
        }
    }
    __syncthreads();

    // pass 2: warp-cooperative fixup; lo recomputed exactly from x
    {
        unsigned cnt = wcnt;
        if (cnt > WLCAP) cnt = WLCAP;
        for (unsigned e = wid; e < cnt; e += 8) {
            unsigned ent = wl[e];
            int rl = (int)(ent >> 16), cc = (int)(ent & 0xFFFF);
            const float* xr = x + (size_t)(rowBase + rl) * 784;
            // 2a: exact lo correction (lo_k = x_k - half_rn(x_k), order-insensitive)
            float part = 0.0f;
            #pragma unroll
            for (int j = 0; j < 25; j++) {
                int k = lane + 32 * j;
                if (k < 784) {
                    float xv = __ldg(xr + k);
                    float lo = xv - __half2float(__float2half_rn(xv));
                    unsigned wb = __ldg(&g_w1p[cc * 25 + j]);
                    part += ((wb >> lane) & 1u) ? lo : -lo;
                }
            }
            #pragma unroll
            for (int o = 16; o; o >>= 1)
                part += __shfl_xor_sync(0xffffffffu, part, o);
            float v = wlv[e] + part;
            if (fabsf(v) >= 1e-3f) {
                if (lane == 0) sb[rl * 256 + cc] = (v >= 0.0f) ? 1 : 0;
            } else {
                // 2b: smem-staged sequential-order oracle (reference-validated)
                float* xbuf = reinterpret_cast<float*>(smem + 24576 + wid * 8192);
                float* gbuf = xbuf + 784;
                for (int k = lane; k < 784; k += 32) {
                    xbuf[k] = __ldg(xr + k);
                    unsigned wb = __ldg(&g_w1p[cc * 25 + (k >> 5)]);
                    gbuf[k] = ((wb >> (k & 31)) & 1u) ? 1.0f : -1.0f;
                }
                __syncwarp();
                if (lane == 0) {
                    float s = 0.0f;
                    #pragma unroll 8
                    for (int k = 0; k < 784; k++)
                        s = fmaf(xbuf[k], gbuf[k], s);
                    sb[rl * 256 + cc] = (s >= 0.0f) ? 1 : 0;
                }
                __syncwarp();
            }
        }
    }
    // load packed w2/w3/w4 while fixup settles
    for (int i = tid; i < 1024; i += 256) sw2[i] = g_w2t[i];
    if (tid < 128) sw3[tid] = g_w3t[tid];
    if (tid < 10)  sw4[tid] = g_w4p[tid];
    __syncthreads();

    // pack 512 words (64 rows x 8 words), 2 per thread -> smem pk
    const unsigned* sbu = reinterpret_cast<const unsigned*>(sb);
    #pragma unroll
    for (int s = 0; s < 2; s++) {
        int q = tid + s * 256;
        int r = q >> 3, w = q & 7;
        unsigned v = 0;
        #pragma unroll
        for (int j = 0; j < 8; j++) {
            unsigned u = sbu[r * 64 + w * 8 + j];
            v |= (((u & 0x01010101u) * 0x01020408u) >> 24) << (j * 4);
        }
        pk[r * 8 + w] = v;
    }
    __syncthreads();

    // ---- fused layers 2-4: warp per row, 8 rows per warp ----
    for (int r = wid; r < 64; r += 8) {
        unsigned a0 = pk[r * 8 + 0], a1 = pk[r * 8 + 1], a2 = pk[r * 8 + 2], a3 = pk[r * 8 + 3];
        unsigned a4 = pk[r * 8 + 4], a5 = pk[r * 8 + 5], a6 = pk[r * 8 + 6], a7 = pk[r * 8 + 7];

        unsigned h2w[4];
        #pragma unroll
        for (int q = 0; q < 4; q++) {
            int j = q * 32 + lane;
            int p = __popc(a0 ^ sw2[0 * 128 + j]) + __popc(a1 ^ sw2[1 * 128 + j])
                  + __popc(a2 ^ sw2[2 * 128 + j]) + __popc(a3 ^ sw2[3 * 128 + j])
                  + __popc(a4 ^ sw2[4 * 128 + j]) + __popc(a5 ^ sw2[5 * 128 + j])
                  + __popc(a6 ^ sw2[6 * 128 + j]) + __popc(a7 ^ sw2[7 * 128 + j]);
            h2w[q] = __ballot_sync(0xffffffffu, (256 - 2 * p) >= 0);
        }

        int p3 = 0;
        #pragma unroll
        for (int w = 0; w < 4; w++) p3 += __popc(h2w[w] ^ sw3[w * 32 + lane]);
        unsigned h3 = __ballot_sync(0xffffffffu, (128 - 2 * p3) >= 0);

        if (lane < 10)
            out[(size_t)(rowBase + r) * 10 + lane] =
                (float)(32 - 2 * __popc(h3 ^ sw4[lane]));
    }
}

// ---------------- launch ------------------------------------------------------
extern "C" void kernel_launch(void* const* d_in, const int* in_sizes, int n_in,
                              void* d_out, int out_size) {
    const float* x  = (const float*)d_in[0];
    const float* w1 = (const float*)d_in[1];
    const float* w2 = (const float*)d_in[2];
    const float* w3 = (const float*)d_in[3];
    const float* w4 = (const float*)d_in[4];
    int M = in_sizes[0] / 784;             // 65536

    cudaFuncSetAttribute(l1_fused, cudaFuncAttributeMaxDynamicSharedMemorySize, SMEM_TOTAL);

    prep_all<<<(53248 + 255) / 256, 256>>>(w1, w2, w3, w4);
    l1_fused<<<M / 64, 256, SMEM_TOTAL>>>(x, w1, (float*)d_out);
}